// round 6
// baseline (speedup 1.0000x reference)
#include <cuda_runtime.h>
#include <cuda_fp16.h>
#include <cstdint>

#define T_   16
#define B_   8192
#define DIN  512
#define DH   1024
#define DOUT 256
#define SPLITK 8
#define KSEG (T_*DH/SPLITK)   // 2048

// ---------------- scratch (allocation-free: __device__ globals) -------------
__device__ __half g_xh [(size_t)B_*DIN];          // x fp16
__device__ __half g_w1t[(size_t)T_*DH*DIN];       // W1^T [t][n][k] fp16
__device__ __half g_w2t[(size_t)T_*DH*DH];        // W2^T [t][n][k] fp16
__device__ __half g_w3t[(size_t)DOUT*T_*DH];      // W3^T [n][t*DH+k] fp16
__device__ __half g_h1 [(size_t)B_*T_*DH];        // h1 [b][t][h] fp16
__device__ __half g_h2 [(size_t)B_*T_*DH];        // h2 [b][t][h] fp16
__device__ float  g_part[(size_t)SPLITK*B_*DOUT]; // split-K partials fp32

// ---------------- helpers ---------------------------------------------------
__device__ __forceinline__ uint32_t smem_to_u32(const void* p) {
    uint32_t a;
    asm("{ .reg .u64 t; cvta.to.shared.u64 t, %1; cvt.u32.u64 %0, t; }"
        : "=r"(a) : "l"(p));
    return a;
}
__device__ __forceinline__ void cp16(uint32_t s, const void* g) {
    asm volatile("cp.async.cg.shared.global [%0], [%1], 16;" :: "r"(s), "l"(g));
}
__device__ __forceinline__ void ldsm4(uint32_t* r, uint32_t addr) {
    asm volatile("ldmatrix.sync.aligned.m8n8.x4.shared.b16 {%0,%1,%2,%3}, [%4];"
        : "=r"(r[0]), "=r"(r[1]), "=r"(r[2]), "=r"(r[3]) : "r"(addr));
}
__device__ __forceinline__ void mma16(float* d, const uint32_t* a,
                                      uint32_t b0, uint32_t b1) {
    asm volatile(
        "mma.sync.aligned.m16n8k16.row.col.f32.f16.f16.f32 "
        "{%0,%1,%2,%3}, {%4,%5,%6,%7}, {%8,%9}, {%0,%1,%2,%3};"
        : "+f"(d[0]), "+f"(d[1]), "+f"(d[2]), "+f"(d[3])
        : "r"(a[0]), "r"(a[1]), "r"(a[2]), "r"(a[3]), "r"(b0), "r"(b1));
}

// ---------------- GEMM kernel ----------------------------------------------
// BM=128, BN=256, BK=64 halves. 512 threads = 16 warps as 2(M) x 8(N),
// warp tile 64x32, m16n8k16 fp16 mma, fp32 accumulate. 3-stage cp.async ring.
constexpr int STAGES      = 3;
constexpr int STAGE_BYTES = (128 + 256) * 128;             // 49152
constexpr int GEMM_SMEM   = STAGES * STAGE_BYTES;          // 147456

// flags: bit0 = add bias, bit1 = relu, bit2 = fp16 output (else fp32)
__global__ void __launch_bounds__(512, 1)
gemm_tc(const __half* __restrict__ A, const __half* __restrict__ B,
        const float* __restrict__ bias, void* __restrict__ Cv,
        int nk, long lda, long ldb, long ldc,
        long a_z, long b_z, long c_z, long bias_z, int flags)
{
    extern __shared__ char smem[];
    const uint32_t sb = smem_to_u32(smem);
    const int tid  = threadIdx.x;
    const int lane = tid & 31;
    const int wid  = tid >> 5;
    const int wm   = wid & 1;        // 2 M warp-rows (64 each)
    const int wn   = wid >> 1;       // 8 N warp-cols (32 each)
    const int z    = blockIdx.z;
    const long m0  = (long)blockIdx.x * 128;
    const long n0  = (long)blockIdx.y * 256;

    const __half* Ag = A + (long)z * a_z + m0 * lda;
    const __half* Bg = B + (long)z * b_z + n0 * ldb;

    // ---- cp.async source pointers / swizzled dest offsets ----
    // One 16B chunk = 8 halves. A: 128 rows x 8 chunks (1024); B: 256 rows (2048).
    const __half* asrc[2]; uint32_t adst[2];
    #pragma unroll
    for (int i = 0; i < 2; i++) {
        int idx = tid + i * 512;
        int r = idx >> 3, c = idx & 7;
        asrc[i] = Ag + (long)r * lda + c * 8;
        adst[i] = (uint32_t)(r * 128 + ((c ^ (r & 7)) << 4));
    }
    const __half* bsrc[4]; uint32_t bdst[4];
    #pragma unroll
    for (int i = 0; i < 4; i++) {
        int idx = tid + i * 512;
        int r = idx >> 3, c = idx & 7;
        bsrc[i] = Bg + (long)r * ldb + c * 8;
        bdst[i] = (uint32_t)(16384 + r * 128 + ((c ^ (r & 7)) << 4));
    }

    // ---- ldmatrix per-thread base offsets ----
    const int rx   = lane & 7;
    const int a_r  = (lane & 7) + (((lane >> 3) & 1) << 3);
    const int a_cs = (lane >> 4) & 1;           // k-half within k16
    const int b_r  = (lane & 7) + (((lane >> 4) & 1) << 3);
    const int b_cs = (lane >> 3) & 1;
    uint32_t aoff[4], boff[2];
    #pragma unroll
    for (int i = 0; i < 4; i++) aoff[i] = (uint32_t)((wm * 64 + i * 16 + a_r) * 128);
    #pragma unroll
    for (int t = 0; t < 2; t++) boff[t] = (uint32_t)(16384 + (wn * 32 + t * 16 + b_r) * 128);

    float acc[4][4][4];
    #pragma unroll
    for (int i = 0; i < 4; i++)
        #pragma unroll
        for (int j = 0; j < 4; j++)
            #pragma unroll
            for (int e = 0; e < 4; e++) acc[i][j][e] = 0.0f;

    // ---- prologue: stages 0..1 ----
    #pragma unroll
    for (int s = 0; s < STAGES - 1; s++) {
        uint32_t base = sb + s * STAGE_BYTES;
        #pragma unroll
        for (int i = 0; i < 2; i++) cp16(base + adst[i], asrc[i] + (long)s * 64);
        #pragma unroll
        for (int i = 0; i < 4; i++) cp16(base + bdst[i], bsrc[i] + (long)s * 64);
        asm volatile("cp.async.commit_group;" ::: "memory");
    }

    int st_c = 0;                     // stage of chunk k
    for (int k = 0; k < nk; k++) {
        if (k < nk - 1) asm volatile("cp.async.wait_group 1;" ::: "memory");
        else            asm volatile("cp.async.wait_group 0;" ::: "memory");
        __syncthreads();

        const int kp = k + STAGES - 1;
        if (kp < nk) {
            int sp = st_c + 2; if (sp >= STAGES) sp -= STAGES;
            uint32_t base = sb + sp * STAGE_BYTES;
            #pragma unroll
            for (int i = 0; i < 2; i++) cp16(base + adst[i], asrc[i] + (long)kp * 64);
            #pragma unroll
            for (int i = 0; i < 4; i++) cp16(base + bdst[i], bsrc[i] + (long)kp * 64);
            asm volatile("cp.async.commit_group;" ::: "memory");
        }

        // compute chunk k (64 K-elems = 4 x k16)
        const uint32_t st = sb + st_c * STAGE_BYTES;
        #pragma unroll
        for (int kk = 0; kk < 4; kk++) {
            uint32_t af[4][4], bf[2][4];
            #pragma unroll
            for (int i = 0; i < 4; i++)
                ldsm4(af[i], st + aoff[i] + (uint32_t)((((kk << 1) + a_cs) ^ rx) << 4));
            #pragma unroll
            for (int t = 0; t < 2; t++)
                ldsm4(bf[t], st + boff[t] + (uint32_t)((((kk << 1) + b_cs) ^ rx) << 4));
            #pragma unroll
            for (int i = 0; i < 4; i++)
                #pragma unroll
                for (int j = 0; j < 4; j++)
                    mma16(acc[i][j], af[i], bf[j >> 1][(j & 1) << 1],
                          bf[j >> 1][((j & 1) << 1) + 1]);
        }
        if (++st_c == STAGES) st_c = 0;
    }

    // ---- epilogue: fused bias / relu, fp16 or fp32 stores ----
    const float* bz = bias + (long)z * bias_z;
    const int g  = lane >> 2;
    const int tg = lane & 3;
    #pragma unroll
    for (int i = 0; i < 4; i++) {
        const long row0 = m0 + wm * 64 + i * 16 + g;
        #pragma unroll
        for (int j = 0; j < 4; j++) {
            const long col = n0 + wn * 32 + j * 8 + tg * 2;
            float2 v0 = make_float2(acc[i][j][0], acc[i][j][1]);
            float2 v1 = make_float2(acc[i][j][2], acc[i][j][3]);
            if (flags & 1) {
                float2 b = *(const float2*)(bz + col);
                v0.x += b.x; v0.y += b.y; v1.x += b.x; v1.y += b.y;
            }
            if (flags & 2) {
                v0.x = fmaxf(v0.x, 0.f); v0.y = fmaxf(v0.y, 0.f);
                v1.x = fmaxf(v1.x, 0.f); v1.y = fmaxf(v1.y, 0.f);
            }
            if (flags & 4) {
                __half* Cz = (__half*)Cv + (long)z * c_z;
                *(__half2*)(Cz + row0 * ldc + col) =
                    __floats2half2_rn(v0.x, v0.y);
                *(__half2*)(Cz + (row0 + 8) * ldc + col) =
                    __floats2half2_rn(v1.x, v1.y);
            } else {
                float* Cz = (float*)Cv + (long)z * c_z;
                *(float2*)(Cz + row0 * ldc + col)       = v0;
                *(float2*)(Cz + (row0 + 8) * ldc + col) = v1;
            }
        }
    }
}

// ---------------- prep / post kernels --------------------------------------
__global__ void cvt_x_h(const float* __restrict__ x, __half* __restrict__ xh) {
    long i = (long)blockIdx.x * 256 + threadIdx.x;     // float4 index
    float4 v = ((const float4*)x)[i];
    ((__half2*)xh)[i * 2 + 0] = __floats2half2_rn(v.x, v.y);
    ((__half2*)xh)[i * 2 + 1] = __floats2half2_rn(v.z, v.w);
}

// in: [z][K][N] fp32 row-major -> out[z*out_z + n*out_ld + z*out_colz + k] fp16
__global__ void transpose_cvt(const float* __restrict__ in, __half* __restrict__ out,
                              int K, int N, long in_z, long out_z,
                              long out_ld, long out_colz)
{
    __shared__ float t[32][33];
    int z = blockIdx.z;
    const float* I = in + (long)z * in_z;
    __half* O = out + (long)z * out_z + (long)z * out_colz;
    int n0 = blockIdx.x * 32, k0 = blockIdx.y * 32;
    int tx = threadIdx.x, ty = threadIdx.y;
    #pragma unroll
    for (int i = 0; i < 32; i += 8)
        t[ty + i][tx] = I[(long)(k0 + ty + i) * N + n0 + tx];
    __syncthreads();
    #pragma unroll
    for (int i = 0; i < 32; i += 8)
        O[(long)(n0 + ty + i) * out_ld + k0 + tx] = __float2half_rn(t[tx][ty + i]);
}

__global__ void reduce_k(const float* __restrict__ part, const float* __restrict__ b3,
                         float* __restrict__ out)
{
    long i = (long)blockIdx.x * 256 + threadIdx.x;   // float4 idx
    float4 a = ((const float4*)part)[i];
    #pragma unroll
    for (int s = 1; s < SPLITK; s++) {
        float4 v = ((const float4*)part)[(long)s * ((long)B_ * DOUT / 4) + i];
        a.x += v.x; a.y += v.y; a.z += v.z; a.w += v.w;
    }
    int o4 = (int)(i & (DOUT / 4 - 1));
    float4 bs = make_float4(0.f, 0.f, 0.f, 0.f);
    #pragma unroll
    for (int t = 0; t < T_; t++) {
        float4 b = ((const float4*)b3)[t * (DOUT / 4) + o4];
        bs.x += b.x; bs.y += b.y; bs.z += b.z; bs.w += b.w;
    }
    const float s = 1.0f / T_;
    float4 o;
    o.x = (a.x + bs.x) * s; o.y = (a.y + bs.y) * s;
    o.z = (a.z + bs.z) * s; o.w = (a.w + bs.w) * s;
    ((float4*)out)[i] = o;
}

// ---------------- launcher --------------------------------------------------
extern "C" void kernel_launch(void* const* d_in, const int* in_sizes, int n_in,
                              void* d_out, int out_size)
{
    const float* x  = (const float*)d_in[0];
    const float* W1 = (const float*)d_in[1];
    const float* b1 = (const float*)d_in[2];
    const float* W2 = (const float*)d_in[3];
    const float* b2 = (const float*)d_in[4];
    const float* W3 = (const float*)d_in[5];
    const float* b3 = (const float*)d_in[6];
    float* out = (float*)d_out;

    __half *xh, *w1t, *w2t, *w3t, *h1, *h2;
    float* part;
    cudaGetSymbolAddress((void**)&xh,   g_xh);
    cudaGetSymbolAddress((void**)&w1t,  g_w1t);
    cudaGetSymbolAddress((void**)&w2t,  g_w2t);
    cudaGetSymbolAddress((void**)&w3t,  g_w3t);
    cudaGetSymbolAddress((void**)&h1,   g_h1);
    cudaGetSymbolAddress((void**)&h2,   g_h2);
    cudaGetSymbolAddress((void**)&part, g_part);

    cudaFuncSetAttribute(gemm_tc, cudaFuncAttributeMaxDynamicSharedMemorySize, GEMM_SMEM);

    // prep: x -> fp16; weights -> fp16 transposed [n][k]
    cvt_x_h<<<(B_ * DIN / 4) / 256, 256>>>(x, xh);
    transpose_cvt<<<dim3(DH / 32, DIN / 32, T_), dim3(32, 8)>>>(
        W1, w1t, DIN, DH, (long)DIN * DH, (long)DH * DIN, DIN, 0);
    transpose_cvt<<<dim3(DH / 32, DH / 32, T_), dim3(32, 8)>>>(
        W2, w2t, DH, DH, (long)DH * DH, (long)DH * DH, DH, 0);
    transpose_cvt<<<dim3(DOUT / 32, DH / 32, T_), dim3(32, 8)>>>(
        W3, w3t, DH, DOUT, (long)DH * DOUT, 0, (long)T_ * DH, DH);

    // L1: h1[b][t*DH+n] = relu(x @ W1[t] + b1[t]),  K=512 -> nk=8
    gemm_tc<<<dim3(B_ / 128, DH / 256, T_), 512, GEMM_SMEM>>>(
        xh, w1t, b1, h1,
        DIN / 64, DIN, DIN, (long)T_ * DH,
        0, (long)DH * DIN, DH, DH, /*flags=*/7);

    // L2: h2[b][t*DH+n] = relu(h1_t @ W2[t] + b2[t]),  K=1024 -> nk=16
    gemm_tc<<<dim3(B_ / 128, DH / 256, T_), 512, GEMM_SMEM>>>(
        h1, w2t, b2, h2,
        DH / 64, (long)T_ * DH, DH, (long)T_ * DH,
        DH, (long)DH * DH, DH, DH, /*flags=*/7);

    // L3: split-K over K=16384 -> fp32 partials (no bias/relu), nk=32
    gemm_tc<<<dim3(B_ / 128, 1, SPLITK), 512, GEMM_SMEM>>>(
        h2, w3t, b3, part,
        KSEG / 64, (long)T_ * DH, (long)T_ * DH, DOUT,
        KSEG, KSEG, (long)B_ * DOUT, 0, /*flags=*/0);

    // reduce partials + mean + summed bias
    reduce_k<<<(B_ * DOUT / 4) / 256, 256>>>(part, b3, out);
}

// round 7
// speedup vs baseline: 1.0909x; 1.0909x over previous
#include <cuda_runtime.h>
#include <cuda_fp16.h>
#include <cstdint>

#define T_   16
#define B_   8192
#define DIN  512
#define DH   1024
#define DOUT 256
#define SPLITK 16
#define KSEG (T_*DH/SPLITK)   // 1024

// ---------------- scratch (allocation-free: __device__ globals) -------------
__device__ __half g_xh [(size_t)B_*DIN];          // x fp16
__device__ __half g_w1t[(size_t)T_*DH*DIN];       // W1^T [t][n][k] fp16
__device__ __half g_w2t[(size_t)T_*DH*DH];        // W2^T [t][n][k] fp16
__device__ __half g_w3t[(size_t)DOUT*T_*DH];      // W3^T [n][t*DH+k] fp16
__device__ __half g_h1 [(size_t)B_*T_*DH];        // h1 [b][t][h] fp16
__device__ __half g_h2 [(size_t)B_*T_*DH];        // h2 [b][t][h] fp16
__device__ float  g_part[(size_t)SPLITK*B_*DOUT]; // split-K partials fp32

// ---------------- helpers ---------------------------------------------------
__device__ __forceinline__ uint32_t smem_to_u32(const void* p) {
    uint32_t a;
    asm("{ .reg .u64 t; cvta.to.shared.u64 t, %1; cvt.u32.u64 %0, t; }"
        : "=r"(a) : "l"(p));
    return a;
}
__device__ __forceinline__ void cp16(uint32_t s, const void* g) {
    asm volatile("cp.async.cg.shared.global [%0], [%1], 16;" :: "r"(s), "l"(g));
}
__device__ __forceinline__ void ldsm4(uint32_t* r, uint32_t addr) {
    asm volatile("ldmatrix.sync.aligned.m8n8.x4.shared.b16 {%0,%1,%2,%3}, [%4];"
        : "=r"(r[0]), "=r"(r[1]), "=r"(r[2]), "=r"(r[3]) : "r"(addr));
}
__device__ __forceinline__ void mma16(float* d, const uint32_t* a,
                                      uint32_t b0, uint32_t b1) {
    asm volatile(
        "mma.sync.aligned.m16n8k16.row.col.f32.f16.f16.f32 "
        "{%0,%1,%2,%3}, {%4,%5,%6,%7}, {%8,%9}, {%0,%1,%2,%3};"
        : "+f"(d[0]), "+f"(d[1]), "+f"(d[2]), "+f"(d[3])
        : "r"(a[0]), "r"(a[1]), "r"(a[2]), "r"(a[3]), "r"(b0), "r"(b1));
}

// ---------------- GEMM kernel ----------------------------------------------
// BM=128, BN=256, BK=64 halves. 256 threads = 8 warps as 2(M) x 4(N),
// warp tile 64x64, m16n8k16 fp16 mma, fp32 accumulate.
// 4-stage cp.async ring; commit-before-wait makes chunk k+1 resident at
// iteration k, enabling full register-level fragment double-buffering
// (every ldmatrix issued one MMA-burst ahead of its consumer).
constexpr int STAGES      = 4;
constexpr int STAGE_BYTES = (128 + 256) * 128;             // 49152
constexpr int GEMM_SMEM   = STAGES * STAGE_BYTES;          // 196608

// flags: bit0 = add bias, bit1 = relu, bit2 = fp16 output (else fp32)
__global__ void __launch_bounds__(256, 1)
gemm_tc(const __half* __restrict__ A, const __half* __restrict__ B,
        const float* __restrict__ bias, void* __restrict__ Cv,
        int nk, long lda, long ldb, long ldc,
        long a_z, long b_z, long c_z, long bias_z, int flags)
{
    extern __shared__ char smem[];
    const uint32_t sb = smem_to_u32(smem);
    const int tid  = threadIdx.x;
    const int lane = tid & 31;
    const int wid  = tid >> 5;
    const int wm   = wid & 1;        // 2 M warp-rows (64 each)
    const int wn   = wid >> 1;       // 4 N warp-cols (64 each)
    const int z    = blockIdx.z;
    const long m0  = (long)blockIdx.x * 128;
    const long n0  = (long)blockIdx.y * 256;

    const __half* Ag = A + (long)z * a_z + m0 * lda;
    const __half* Bg = B + (long)z * b_z + n0 * ldb;

    // ---- cp.async source pointers / swizzled dest offsets ----
    const __half* asrc[4]; uint32_t adst[4];
    #pragma unroll
    for (int i = 0; i < 4; i++) {
        int idx = tid + i * 256;
        int r = idx >> 3, c = idx & 7;
        asrc[i] = Ag + (long)r * lda + c * 8;
        adst[i] = (uint32_t)(r * 128 + ((c ^ (r & 7)) << 4));
    }
    const __half* bsrc[8]; uint32_t bdst[8];
    #pragma unroll
    for (int i = 0; i < 8; i++) {
        int idx = tid + i * 256;
        int r = idx >> 3, c = idx & 7;
        bsrc[i] = Bg + (long)r * ldb + c * 8;
        bdst[i] = (uint32_t)(16384 + r * 128 + ((c ^ (r & 7)) << 4));
    }

    // ---- ldmatrix per-thread base offsets ----
    const int rx   = lane & 7;
    const int a_r  = (lane & 7) + (((lane >> 3) & 1) << 3);
    const int a_cs = (lane >> 4) & 1;           // k-half within k16
    const int b_r  = (lane & 7) + (((lane >> 4) & 1) << 3);
    const int b_cs = (lane >> 3) & 1;
    uint32_t aoff[4], boff[4];
    #pragma unroll
    for (int i = 0; i < 4; i++) aoff[i] = (uint32_t)((wm * 64 + i * 16 + a_r) * 128);
    #pragma unroll
    for (int t = 0; t < 4; t++) boff[t] = (uint32_t)(16384 + (wn * 64 + t * 16 + b_r) * 128);

    float acc[4][8][4];
    #pragma unroll
    for (int i = 0; i < 4; i++)
        #pragma unroll
        for (int j = 0; j < 8; j++)
            #pragma unroll
            for (int e = 0; e < 4; e++) acc[i][j][e] = 0.0f;

    auto ldf = [&](uint32_t stb, int kk, uint32_t af[4][4], uint32_t bf[4][4]) {
        #pragma unroll
        for (int i = 0; i < 4; i++)
            ldsm4(af[i], stb + aoff[i] + (uint32_t)((((kk << 1) + a_cs) ^ rx) << 4));
        #pragma unroll
        for (int t = 0; t < 4; t++)
            ldsm4(bf[t], stb + boff[t] + (uint32_t)((((kk << 1) + b_cs) ^ rx) << 4));
    };

    // ---- prologue: chunks 0,1 -> stages 0,1 ----
    #pragma unroll
    for (int s = 0; s < 2; s++) {
        uint32_t base = sb + s * STAGE_BYTES;
        #pragma unroll
        for (int i = 0; i < 4; i++) cp16(base + adst[i], asrc[i] + (long)s * 64);
        #pragma unroll
        for (int i = 0; i < 8; i++) cp16(base + bdst[i], bsrc[i] + (long)s * 64);
        asm volatile("cp.async.commit_group;" ::: "memory");
    }

    uint32_t afb[2][4][4], bfb[2][4][4];

    for (int k = 0; k < nk; k++) {
        // commit chunk k+2 BEFORE the wait: its stage was last read at iter k-2
        // (protected by the barrier at iter k-1), and committing first makes
        // wait_group 1 guarantee chunks <= k+1 are resident.
        const int kp = k + 2;
        if (kp < nk) {
            uint32_t base = sb + (kp & 3) * STAGE_BYTES;
            #pragma unroll
            for (int i = 0; i < 4; i++) cp16(base + adst[i], asrc[i] + (long)kp * 64);
            #pragma unroll
            for (int i = 0; i < 8; i++) cp16(base + bdst[i], bsrc[i] + (long)kp * 64);
            asm volatile("cp.async.commit_group;" ::: "memory");
        }
        if (k < nk - 2) asm volatile("cp.async.wait_group 1;" ::: "memory");
        else            asm volatile("cp.async.wait_group 0;" ::: "memory");
        __syncthreads();

        const uint32_t stc = sb + (k & 3) * STAGE_BYTES;
        if (k == 0) ldf(stc, 0, afb[0], bfb[0]);   // cold start: chunk 0, kk 0

        #pragma unroll
        for (int kk = 0; kk < 4; kk++) {
            const int cur = kk & 1;
            // prefetch one MMA-burst ahead (next kk, or next chunk's kk=0)
            if (kk < 3)           ldf(stc, kk + 1, afb[cur ^ 1], bfb[cur ^ 1]);
            else if (k + 1 < nk)  ldf(sb + ((k + 1) & 3) * STAGE_BYTES, 0,
                                      afb[cur ^ 1], bfb[cur ^ 1]);
            #pragma unroll
            for (int i = 0; i < 4; i++)
                #pragma unroll
                for (int j = 0; j < 8; j++)
                    mma16(acc[i][j], afb[cur][i],
                          bfb[cur][j >> 1][(j & 1) << 1],
                          bfb[cur][j >> 1][((j & 1) << 1) + 1]);
        }
    }

    // ---- epilogue: fused bias / relu, fp16 or fp32 stores ----
    const float* bz = bias + (long)z * bias_z;
    const int g  = lane >> 2;
    const int tg = lane & 3;
    #pragma unroll
    for (int i = 0; i < 4; i++) {
        const long row0 = m0 + wm * 64 + i * 16 + g;
        #pragma unroll
        for (int j = 0; j < 8; j++) {
            const long col = n0 + wn * 64 + j * 8 + tg * 2;
            float2 v0 = make_float2(acc[i][j][0], acc[i][j][1]);
            float2 v1 = make_float2(acc[i][j][2], acc[i][j][3]);
            if (flags & 1) {
                float2 b = *(const float2*)(bz + col);
                v0.x += b.x; v0.y += b.y; v1.x += b.x; v1.y += b.y;
            }
            if (flags & 2) {
                v0.x = fmaxf(v0.x, 0.f); v0.y = fmaxf(v0.y, 0.f);
                v1.x = fmaxf(v1.x, 0.f); v1.y = fmaxf(v1.y, 0.f);
            }
            if (flags & 4) {
                __half* Cz = (__half*)Cv + (long)z * c_z;
                *(__half2*)(Cz + row0 * ldc + col) =
                    __floats2half2_rn(v0.x, v0.y);
                *(__half2*)(Cz + (row0 + 8) * ldc + col) =
                    __floats2half2_rn(v1.x, v1.y);
            } else {
                float* Cz = (float*)Cv + (long)z * c_z;
                *(float2*)(Cz + row0 * ldc + col)       = v0;
                *(float2*)(Cz + (row0 + 8) * ldc + col) = v1;
            }
        }
    }
}

// ---------------- prep / post kernels --------------------------------------
__global__ void cvt_x_h(const float* __restrict__ x, __half* __restrict__ xh) {
    long i = (long)blockIdx.x * 256 + threadIdx.x;     // float4 index
    float4 v = ((const float4*)x)[i];
    ((__half2*)xh)[i * 2 + 0] = __floats2half2_rn(v.x, v.y);
    ((__half2*)xh)[i * 2 + 1] = __floats2half2_rn(v.z, v.w);
}

// in: [z][K][N] fp32 row-major -> out[z*out_z + n*out_ld + z*out_colz + k] fp16
__global__ void transpose_cvt(const float* __restrict__ in, __half* __restrict__ out,
                              int K, int N, long in_z, long out_z,
                              long out_ld, long out_colz)
{
    __shared__ float t[32][33];
    int z = blockIdx.z;
    const float* I = in + (long)z * in_z;
    __half* O = out + (long)z * out_z + (long)z * out_colz;
    int n0 = blockIdx.x * 32, k0 = blockIdx.y * 32;
    int tx = threadIdx.x, ty = threadIdx.y;
    #pragma unroll
    for (int i = 0; i < 32; i += 8)
        t[ty + i][tx] = I[(long)(k0 + ty + i) * N + n0 + tx];
    __syncthreads();
    #pragma unroll
    for (int i = 0; i < 32; i += 8)
        O[(long)(n0 + ty + i) * out_ld + k0 + tx] = __float2half_rn(t[tx][ty + i]);
}

__global__ void reduce_k(const float* __restrict__ part, const float* __restrict__ b3,
                         float* __restrict__ out)
{
    long i = (long)blockIdx.x * 256 + threadIdx.x;   // float4 idx
    float4 a = ((const float4*)part)[i];
    #pragma unroll
    for (int s = 1; s < SPLITK; s++) {
        float4 v = ((const float4*)part)[(long)s * ((long)B_ * DOUT / 4) + i];
        a.x += v.x; a.y += v.y; a.z += v.z; a.w += v.w;
    }
    int o4 = (int)(i & (DOUT / 4 - 1));
    float4 bs = make_float4(0.f, 0.f, 0.f, 0.f);
    #pragma unroll
    for (int t = 0; t < T_; t++) {
        float4 b = ((const float4*)b3)[t * (DOUT / 4) + o4];
        bs.x += b.x; bs.y += b.y; bs.z += b.z; bs.w += b.w;
    }
    const float s = 1.0f / T_;
    float4 o;
    o.x = (a.x + bs.x) * s; o.y = (a.y + bs.y) * s;
    o.z = (a.z + bs.z) * s; o.w = (a.w + bs.w) * s;
    ((float4*)out)[i] = o;
}

// ---------------- launcher --------------------------------------------------
extern "C" void kernel_launch(void* const* d_in, const int* in_sizes, int n_in,
                              void* d_out, int out_size)
{
    const float* x  = (const float*)d_in[0];
    const float* W1 = (const float*)d_in[1];
    const float* b1 = (const float*)d_in[2];
    const float* W2 = (const float*)d_in[3];
    const float* b2 = (const float*)d_in[4];
    const float* W3 = (const float*)d_in[5];
    const float* b3 = (const float*)d_in[6];
    float* out = (float*)d_out;

    __half *xh, *w1t, *w2t, *w3t, *h1, *h2;
    float* part;
    cudaGetSymbolAddress((void**)&xh,   g_xh);
    cudaGetSymbolAddress((void**)&w1t,  g_w1t);
    cudaGetSymbolAddress((void**)&w2t,  g_w2t);
    cudaGetSymbolAddress((void**)&w3t,  g_w3t);
    cudaGetSymbolAddress((void**)&h1,   g_h1);
    cudaGetSymbolAddress((void**)&h2,   g_h2);
    cudaGetSymbolAddress((void**)&part, g_part);

    cudaFuncSetAttribute(gemm_tc, cudaFuncAttributeMaxDynamicSharedMemorySize, GEMM_SMEM);

    // prep: x -> fp16; weights -> fp16 transposed [n][k]
    cvt_x_h<<<(B_ * DIN / 4) / 256, 256>>>(x, xh);
    transpose_cvt<<<dim3(DH / 32, DIN / 32, T_), dim3(32, 8)>>>(
        W1, w1t, DIN, DH, (long)DIN * DH, (long)DH * DIN, DIN, 0);
    transpose_cvt<<<dim3(DH / 32, DH / 32, T_), dim3(32, 8)>>>(
        W2, w2t, DH, DH, (long)DH * DH, (long)DH * DH, DH, 0);
    transpose_cvt<<<dim3(DOUT / 32, DH / 32, T_), dim3(32, 8)>>>(
        W3, w3t, DH, DOUT, (long)DH * DOUT, 0, (long)T_ * DH, DH);

    // L1: h1[b][t*DH+n] = relu(x @ W1[t] + b1[t]),  K=512 -> nk=8
    gemm_tc<<<dim3(B_ / 128, DH / 256, T_), 256, GEMM_SMEM>>>(
        xh, w1t, b1, h1,
        DIN / 64, DIN, DIN, (long)T_ * DH,
        0, (long)DH * DIN, DH, DH, /*flags=*/7);

    // L2: h2[b][t*DH+n] = relu(h1_t @ W2[t] + b2[t]),  K=1024 -> nk=16
    gemm_tc<<<dim3(B_ / 128, DH / 256, T_), 256, GEMM_SMEM>>>(
        h1, w2t, b2, h2,
        DH / 64, (long)T_ * DH, DH, (long)T_ * DH,
        DH, (long)DH * DH, DH, DH, /*flags=*/7);

    // L3: split-K over K=16384 -> fp32 partials (no bias/relu), nk=16
    gemm_tc<<<dim3(B_ / 128, 1, SPLITK), 256, GEMM_SMEM>>>(
        h2, w3t, b3, part,
        KSEG / 64, (long)T_ * DH, (long)T_ * DH, DOUT,
        KSEG, KSEG, (long)B_ * DOUT, 0, /*flags=*/0);

    // reduce partials + mean + summed bias
    reduce_k<<<(B_ * DOUT / 4) / 256, 256>>>(part, b3, out);
}